// round 1
// baseline (speedup 1.0000x reference)
#include <cuda_runtime.h>

// PillarFeatureNet on GB300 (sm_103a)
// Round 1: fp32 warp-per-pillar baseline with BN folding + 7-feature trick.

#define C_MID 64
#define C_OUT 64
#define MPTS  32
#define WARPS_PER_BLK 8
#define THREADS (WARPS_PER_BLK * 32)

__constant__ float c_RES  = 0.16f;
__constant__ float c_XMIN = -51.2f;
__constant__ float c_YMIN = -51.2f;

#define EPSV 1e-5f
#define NEGV -1000000000.0f

// Folded weights (device scratch; no allocations allowed)
__device__ float g_W1f[7 * C_MID];      // [i][j], i in 0..6 (xo/yo rows merged)
__device__ float g_b1f[C_MID];
__device__ float g_W2t[C_OUT * C_MID];  // transposed: [c][k]
__device__ float g_b2f[C_OUT];

// ---------------------------------------------------------------------------
// Fold BN scale/shift into weights+bias; merge duplicated feature rows; transpose W2.
// Launch with 1 block of 64 threads.
__global__ void fold_kernel(const float* __restrict__ W1, const float* __restrict__ b1,
                            const float* __restrict__ g1, const float* __restrict__ beta1,
                            const float* __restrict__ m1, const float* __restrict__ v1,
                            const float* __restrict__ W2, const float* __restrict__ b2,
                            const float* __restrict__ g2, const float* __restrict__ beta2,
                            const float* __restrict__ m2, const float* __restrict__ v2)
{
    int c = threadIdx.x;  // 0..63
    float s1 = g1[c] * rsqrtf(v1[c] + EPSV);
    g_b1f[c] = (b1[c] - m1[c]) * s1 + beta1[c];
#pragma unroll
    for (int i = 0; i < 7; i++) {
        float w = W1[i * C_MID + c];
        if (i == 4) w += W1[7 * C_MID + c];  // xo appears at rows 4 and 7
        if (i == 5) w += W1[8 * C_MID + c];  // yo appears at rows 5 and 8
        g_W1f[i * C_MID + c] = w * s1;
    }
    float s2 = g2[c] * rsqrtf(v2[c] + EPSV);
    g_b2f[c] = (b2[c] - m2[c]) * s2 + beta2[c];
#pragma unroll
    for (int k = 0; k < C_MID; k++) {
        g_W2t[c * C_MID + k] = W2[k * C_OUT + c] * s2;  // [c][k] layout
    }
}

// ---------------------------------------------------------------------------
// Main kernel: one warp per pillar, one lane per point.
__global__ __launch_bounds__(THREADS)
void pfn_kernel(const float4* __restrict__ pillars,   // [P*32] of (x,y,z,r)
                const int* __restrict__ coords,       // [P*2]  (row, col)
                const int* __restrict__ npts_arr,     // [P]
                float* __restrict__ out,              // [P*64]
                int P)
{
    __shared__ float sW1[7 * C_MID];
    __shared__ float sb1[C_MID];
    __shared__ float sW2[C_OUT * C_MID];   // [c][k]
    __shared__ float sb2[C_OUT];
    __shared__ float sOut[WARPS_PER_BLK][C_OUT];

    int tid = threadIdx.x;
    for (int i = tid; i < 7 * C_MID; i += THREADS) sW1[i] = g_W1f[i];
    if (tid < C_MID) { sb1[tid] = g_b1f[tid]; sb2[tid] = g_b2f[tid]; }
    for (int i = tid; i < C_OUT * C_MID; i += THREADS) sW2[i] = g_W2t[i];
    __syncthreads();

    int warp = tid >> 5;
    int lane = tid & 31;
    int p = blockIdx.x * WARPS_PER_BLK + warp;
    if (p >= P) return;  // per-warp uniform; no further block-level syncs below

    // Per-point raw data (coalesced 16B loads)
    float4 pt = pillars[(size_t)p * MPTS + lane];

    int cy = coords[2 * p + 0];
    int cx = coords[2 * p + 1];
    int np = npts_arr[p];
    bool active = (lane < np);

    // masked z-mean across the warp
    float zs = active ? pt.z : 0.0f;
#pragma unroll
    for (int off = 16; off; off >>= 1) zs += __shfl_xor_sync(0xffffffffu, zs, off);
    float zmean = zs / (float)max(np, 1);

    float xc = ((float)cx + 0.5f) * c_RES + c_XMIN;
    float yc = ((float)cy + 0.5f) * c_RES + c_YMIN;

    float f0 = pt.x, f1 = pt.y, f2 = pt.z, f3 = pt.w;
    float f4 = pt.x - xc;
    float f5 = pt.y - yc;
    float f6 = pt.z - zmean;

    // ---- Layer 1: h1[j] = relu(sum_i f[i]*W1f[i][j] + b1f[j]) ----
    float h1[C_MID];
#pragma unroll
    for (int j4 = 0; j4 < C_MID / 4; j4++) {
        float4 a = *(const float4*)(sb1 + j4 * 4);
        const float* w;
        w = sW1 + 0 * C_MID + j4 * 4; { float4 wv = *(const float4*)w;
            a.x = fmaf(f0, wv.x, a.x); a.y = fmaf(f0, wv.y, a.y);
            a.z = fmaf(f0, wv.z, a.z); a.w = fmaf(f0, wv.w, a.w); }
        w = sW1 + 1 * C_MID + j4 * 4; { float4 wv = *(const float4*)w;
            a.x = fmaf(f1, wv.x, a.x); a.y = fmaf(f1, wv.y, a.y);
            a.z = fmaf(f1, wv.z, a.z); a.w = fmaf(f1, wv.w, a.w); }
        w = sW1 + 2 * C_MID + j4 * 4; { float4 wv = *(const float4*)w;
            a.x = fmaf(f2, wv.x, a.x); a.y = fmaf(f2, wv.y, a.y);
            a.z = fmaf(f2, wv.z, a.z); a.w = fmaf(f2, wv.w, a.w); }
        w = sW1 + 3 * C_MID + j4 * 4; { float4 wv = *(const float4*)w;
            a.x = fmaf(f3, wv.x, a.x); a.y = fmaf(f3, wv.y, a.y);
            a.z = fmaf(f3, wv.z, a.z); a.w = fmaf(f3, wv.w, a.w); }
        w = sW1 + 4 * C_MID + j4 * 4; { float4 wv = *(const float4*)w;
            a.x = fmaf(f4, wv.x, a.x); a.y = fmaf(f4, wv.y, a.y);
            a.z = fmaf(f4, wv.z, a.z); a.w = fmaf(f4, wv.w, a.w); }
        w = sW1 + 5 * C_MID + j4 * 4; { float4 wv = *(const float4*)w;
            a.x = fmaf(f5, wv.x, a.x); a.y = fmaf(f5, wv.y, a.y);
            a.z = fmaf(f5, wv.z, a.z); a.w = fmaf(f5, wv.w, a.w); }
        w = sW1 + 6 * C_MID + j4 * 4; { float4 wv = *(const float4*)w;
            a.x = fmaf(f6, wv.x, a.x); a.y = fmaf(f6, wv.y, a.y);
            a.z = fmaf(f6, wv.z, a.z); a.w = fmaf(f6, wv.w, a.w); }
        h1[j4 * 4 + 0] = fmaxf(a.x, 0.0f);
        h1[j4 * 4 + 1] = fmaxf(a.y, 0.0f);
        h1[j4 * 4 + 2] = fmaxf(a.z, 0.0f);
        h1[j4 * 4 + 3] = fmaxf(a.w, 0.0f);
    }

    // ---- Layer 2 + relu + mask + warp max ----
    for (int c = 0; c < C_OUT; c++) {
        const float4* w4 = (const float4*)(sW2 + c * C_MID);
        float a0 = sb2[c], a1 = 0.0f, a2 = 0.0f, a3 = 0.0f;
#pragma unroll
        for (int k = 0; k < C_MID / 4; k++) {
            float4 wv = w4[k];
            a0 = fmaf(h1[4 * k + 0], wv.x, a0);
            a1 = fmaf(h1[4 * k + 1], wv.y, a1);
            a2 = fmaf(h1[4 * k + 2], wv.z, a2);
            a3 = fmaf(h1[4 * k + 3], wv.w, a3);
        }
        float v = fmaxf((a0 + a1) + (a2 + a3), 0.0f);
        v = active ? v : NEGV;
#pragma unroll
        for (int off = 16; off; off >>= 1)
            v = fmaxf(v, __shfl_xor_sync(0xffffffffu, v, off));
        if (lane == 0) sOut[warp][c] = v;
    }
    __syncwarp();

    // coalesced store: 64 floats per pillar
    out[(size_t)p * C_OUT + lane]      = sOut[warp][lane];
    out[(size_t)p * C_OUT + 32 + lane] = sOut[warp][32 + lane];
}

// ---------------------------------------------------------------------------
extern "C" void kernel_launch(void* const* d_in, const int* in_sizes, int n_in,
                              void* d_out, int out_size)
{
    // metadata order:
    // 0 pillars [P,32,4] f32, 1 pillar_coords [P,2] i32, 2 num_points [P] i32,
    // 3 W1 [9,64], 4 b1, 5 g1, 6 beta1, 7 m1, 8 v1,
    // 9 W2 [64,64], 10 b2, 11 g2, 12 beta2, 13 m2, 14 v2
    const float4* pillars = (const float4*)d_in[0];
    const int*    coords  = (const int*)d_in[1];
    const int*    npts    = (const int*)d_in[2];
    const float*  W1 = (const float*)d_in[3];
    const float*  b1 = (const float*)d_in[4];
    const float*  g1 = (const float*)d_in[5];
    const float*  be1 = (const float*)d_in[6];
    const float*  m1 = (const float*)d_in[7];
    const float*  v1 = (const float*)d_in[8];
    const float*  W2 = (const float*)d_in[9];
    const float*  b2 = (const float*)d_in[10];
    const float*  g2 = (const float*)d_in[11];
    const float*  be2 = (const float*)d_in[12];
    const float*  m2 = (const float*)d_in[13];
    const float*  v2 = (const float*)d_in[14];

    int P = in_sizes[0] / (MPTS * 4);

    fold_kernel<<<1, 64>>>(W1, b1, g1, be1, m1, v1, W2, b2, g2, be2, m2, v2);

    int blocks = (P + WARPS_PER_BLK - 1) / WARPS_PER_BLK;
    pfn_kernel<<<blocks, THREADS>>>(pillars, coords, npts, (float*)d_out, P);
}

// round 12
// speedup vs baseline: 4.1309x; 4.1309x over previous
#include <cuda_runtime.h>
#include <cuda_bf16.h>
#include <cstdint>

#define MPTS 32
#define NEGV -1000000000.0f
#define EPSV 1e-5f

// ---------------- dynamic smem layout ----------------
// [0, 8192)        sW2 hi  : bf16 [n=64][k=64], chunk-swizzled rows (128B/row)
// [8192, 16384)    sW2 lo
// [16384, 49152)   per-warp h1 buffers: warp w at 16384 + w*8192 (hi 4KB, lo 4KB)
// [49152, 50944)   sW1: 7*64 f32
// [50944, 51200)   sb1: 64 f32
// [51200, 51456)   sb2: 64 f32
#define OFF_W2H 0
#define OFF_W2L 8192
#define OFF_H1  16384
#define OFF_W1  49152
#define OFF_SB1 50944
#define OFF_SB2 51200
#define DYN_SMEM 51456

// ---------------- folded weights (device scratch) ----------------
__device__ float g_W1f[7 * 64];
__device__ float g_b1f[64];
__device__ float g_b2f[64];
// bf16 [n][k] images, row = n (128 bytes), 16B-chunk swizzled: chunk' = chunk ^ (n&7)
__device__ __align__(16) unsigned short g_W2th[64 * 64];
__device__ __align__(16) unsigned short g_W2tl[64 * 64];

// ---------------- helpers ----------------
__device__ __forceinline__ uint32_t smem_u32(const void* p) {
    uint32_t a;
    asm("{ .reg .u64 t; cvta.to.shared.u64 t, %1; cvt.u32.u64 %0, t; }" : "=r"(a) : "l"(p));
    return a;
}
__device__ __forceinline__ void ldmx4(uint32_t* r, uint32_t addr) {
    asm volatile("ldmatrix.sync.aligned.m8n8.x4.shared.b16 {%0,%1,%2,%3}, [%4];"
                 : "=r"(r[0]), "=r"(r[1]), "=r"(r[2]), "=r"(r[3]) : "r"(addr));
}
__device__ __forceinline__ void mma16816(float* c, const uint32_t* a, const uint32_t* b) {
    asm volatile("mma.sync.aligned.m16n8k16.row.col.f32.bf16.bf16.f32 "
                 "{%0,%1,%2,%3}, {%4,%5,%6,%7}, {%8,%9}, {%0,%1,%2,%3};"
                 : "+f"(c[0]), "+f"(c[1]), "+f"(c[2]), "+f"(c[3])
                 : "r"(a[0]), "r"(a[1]), "r"(a[2]), "r"(a[3]), "r"(b[0]), "r"(b[1]));
}

// ---------------------------------------------------------------------------
// Fold kernel: BN-fold, merge duplicate feature rows, build bf16 hi/lo W2^T
// images with the ldmatrix swizzle baked in.  <<<1, 64>>>
__global__ void fold_kernel(const float* __restrict__ W1, const float* __restrict__ b1,
                            const float* __restrict__ g1, const float* __restrict__ beta1,
                            const float* __restrict__ m1, const float* __restrict__ v1,
                            const float* __restrict__ W2, const float* __restrict__ b2,
                            const float* __restrict__ g2, const float* __restrict__ beta2,
                            const float* __restrict__ m2, const float* __restrict__ v2)
{
    int c = threadIdx.x;  // 0..63 (output channel n / mid channel)
    float s1 = g1[c] * rsqrtf(v1[c] + EPSV);
    g_b1f[c] = (b1[c] - m1[c]) * s1 + beta1[c];
#pragma unroll
    for (int i = 0; i < 7; i++) {
        float w = W1[i * 64 + c];
        if (i == 4) w += W1[7 * 64 + c];  // xo duplicated at rows 4,7
        if (i == 5) w += W1[8 * 64 + c];  // yo duplicated at rows 5,8
        g_W1f[i * 64 + c] = w * s1;
    }
    float s2 = g2[c] * rsqrtf(v2[c] + EPSV);
    g_b2f[c] = (b2[c] - m2[c]) * s2 + beta2[c];
    // Row n=c of W2^T: element k, stored at swizzled chunk position
    for (int k = 0; k < 64; k++) {
        float w = W2[k * 64 + c] * s2;
        __nv_bfloat16 hb = __float2bfloat16_rn(w);
        float lo = w - __bfloat162float(hb);
        __nv_bfloat16 lb = __float2bfloat16_rn(lo);
        int chunk = (k >> 3) ^ (c & 7);                 // 16B chunk swizzle
        int idx = c * 64 + chunk * 8 + (k & 7);
        g_W2th[idx] = *reinterpret_cast<unsigned short*>(&hb);
        g_W2tl[idx] = *reinterpret_cast<unsigned short*>(&lb);
    }
}

// ---------------------------------------------------------------------------
// Main kernel: warp = pillar; 4 warps/CTA; persistent grid; no CTA syncs in loop.
extern "C" __global__ void __launch_bounds__(128, 3)
pfn_mma_kernel(const float4* __restrict__ pillars,
               const int* __restrict__ coords,
               const int* __restrict__ npts_arr,
               float* __restrict__ out,
               int P, int ntiles)
{
    extern __shared__ char smem[];
    uint32_t sbase = smem_u32(smem);
    int tid = threadIdx.x, warp = tid >> 5, lane = tid & 31;

    // ---- stage weights (once) ----
    for (int i = tid; i < 512; i += 128) {
        ((uint4*)(smem + OFF_W2H))[i] = ((const uint4*)g_W2th)[i];
        ((uint4*)(smem + OFF_W2L))[i] = ((const uint4*)g_W2tl)[i];
    }
    for (int i = tid; i < 7 * 64; i += 128) ((float*)(smem + OFF_W1))[i] = g_W1f[i];
    if (tid < 64) {
        ((float*)(smem + OFF_SB1))[tid] = g_b1f[tid];
        ((float*)(smem + OFF_SB2))[tid] = g_b2f[tid];
    }
    __syncthreads();

    const float* sW1 = (const float*)(smem + OFF_W1);
    const float* sb1 = (const float*)(smem + OFF_SB1);
    const float* sb2 = (const float*)(smem + OFF_SB2);

    uint32_t h1h = sbase + OFF_H1 + warp * 8192;
    uint32_t h1l = h1h + 4096;
    uint32_t w2h = sbase + OFF_W2H;
    uint32_t w2l = sbase + OFF_W2L;

    // per-lane ldmatrix address components
    int l7 = lane & 7;
    int asub = lane >> 3;                      // A: sub-tile id 0..3
    int arow = ((asub & 1) << 3) + l7;         // row within 16-row m-tile
    int achk = asub >> 1;                      // k-chunk half (0/1)
    int bsub = lane >> 3;                      // B: sub-tile id 0..3
    int brow = ((bsub >> 1) << 3) + l7;        // n-row within 16-row pair
    int bchk = bsub & 1;

    int gr = lane >> 2;                        // fragment row 0..7
    int gc = (lane & 3) * 2;                   // fragment col pair base

    for (int tile = blockIdx.x; tile < ntiles; tile += gridDim.x) {
        int p = tile * 4 + warp;
        if (p >= P) continue;                  // warp-uniform

        // ---- load point / pillar data ----
        float4 pt = pillars[(size_t)p * MPTS + lane];
        int cy = coords[2 * p + 0];
        int cx = coords[2 * p + 1];
        int np = npts_arr[p];
        bool active = lane < np;

        float zs = active ? pt.z : 0.0f;
#pragma unroll
        for (int off = 16; off; off >>= 1) zs += __shfl_xor_sync(0xffffffffu, zs, off);
        float zmean = zs / (float)max(np, 1);

        float xc = ((float)cx + 0.5f) * 0.16f + (-51.2f);
        float yc = ((float)cy + 0.5f) * 0.16f + (-51.2f);
        float f0 = pt.x, f1 = pt.y, f2 = pt.z, f3 = pt.w;
        float f4 = pt.x - xc, f5 = pt.y - yc, f6 = pt.z - zmean;

        // ---- Layer 1 (exact fp32; verified in R1) ----
        float h1[64];
#pragma unroll
        for (int j4 = 0; j4 < 16; j4++) {
            float4 a = *(const float4*)(sb1 + j4 * 4);
            float4 wv;
            wv = *(const float4*)(sW1 + 0 * 64 + j4 * 4);
            a.x = fmaf(f0, wv.x, a.x); a.y = fmaf(f0, wv.y, a.y); a.z = fmaf(f0, wv.z, a.z); a.w = fmaf(f0, wv.w, a.w);
            wv = *(const float4*)(sW1 + 1 * 64 + j4 * 4);
            a.x = fmaf(f1, wv.x, a.x); a.y = fmaf(f1, wv.y, a.y); a.z = fmaf(f1, wv.z, a.z); a.w = fmaf(f1, wv.w, a.w);
            wv = *(const float4*)(sW1 + 2 * 64 + j4 * 4);
            a.x = fmaf(f2, wv.x, a.x); a.y = fmaf(f2, wv.y, a.y); a.z = fmaf(f2, wv.z, a.z); a.w = fmaf(f2, wv.w, a.w);
            wv = *(const float4*)(sW1 + 3 * 64 + j4 * 4);
            a.x = fmaf(f3, wv.x, a.x); a.y = fmaf(f3, wv.y, a.y); a.z = fmaf(f3, wv.z, a.z); a.w = fmaf(f3, wv.w, a.w);
            wv = *(const float4*)(sW1 + 4 * 64 + j4 * 4);
            a.x = fmaf(f4, wv.x, a.x); a.y = fmaf(f4, wv.y, a.y); a.z = fmaf(f4, wv.z, a.z); a.w = fmaf(f4, wv.w, a.w);
            wv = *(const float4*)(sW1 + 5 * 64 + j4 * 4);
            a.x = fmaf(f5, wv.x, a.x); a.y = fmaf(f5, wv.y, a.y); a.z = fmaf(f5, wv.z, a.z); a.w = fmaf(f5, wv.w, a.w);
            wv = *(const float4*)(sW1 + 6 * 64 + j4 * 4);
            a.x = fmaf(f6, wv.x, a.x); a.y = fmaf(f6, wv.y, a.y); a.z = fmaf(f6, wv.z, a.z); a.w = fmaf(f6, wv.w, a.w);
            h1[j4 * 4 + 0] = fmaxf(a.x, 0.0f);
            h1[j4 * 4 + 1] = fmaxf(a.y, 0.0f);
            h1[j4 * 4 + 2] = fmaxf(a.z, 0.0f);
            h1[j4 * 4 + 3] = fmaxf(a.w, 0.0f);
        }

        // ---- bf16 hi/lo split, swizzled store to per-warp smem ----
        {
            uint32_t ah[32], al[32];
#pragma unroll
            for (int i = 0; i < 32; i++) {
                float a = h1[2 * i], b = h1[2 * i + 1];
                __nv_bfloat162 hp = __floats2bfloat162_rn(a, b);  // lo=a, hi=b
                ah[i] = *reinterpret_cast<uint32_t*>(&hp);
                float la = a - __bfloat162float(hp.x);
                float lb = b - __bfloat162float(hp.y);
                __nv_bfloat162 lp = __floats2bfloat162_rn(la, lb);
                al[i] = *reinterpret_cast<uint32_t*>(&lp);
            }
            char* hh = smem + OFF_H1 + warp * 8192;
            char* hl = hh + 4096;
#pragma unroll
            for (int i = 0; i < 8; i++) {                 // chunk i = ch 8i..8i+7
                int sw = ((i ^ (lane & 7)) << 4) + lane * 128;
                *(uint4*)(hh + sw) = make_uint4(ah[4 * i], ah[4 * i + 1], ah[4 * i + 2], ah[4 * i + 3]);
                *(uint4*)(hl + sw) = make_uint4(al[4 * i], al[4 * i + 1], al[4 * i + 2], al[4 * i + 3]);
            }
        }
        __syncwarp();

        // ---- Layer 2: 3-pass bf16 mma (AhBh + AhBl + AlBh) ----
        float c[2][8][4];
#pragma unroll
        for (int mt = 0; mt < 2; mt++)
#pragma unroll
            for (int nt = 0; nt < 8; nt++)
#pragma unroll
                for (int e = 0; e < 4; e++) c[mt][nt][e] = 0.0f;

#pragma unroll
        for (int kt = 0; kt < 4; kt++) {
            // A fragments (mt = 0,1; hi and lo)
            uint32_t ah0[4], ah1[4], al0[4], al1[4];
            {
                int chunk = kt * 2 + achk;
                uint32_t sw = ((uint32_t)(chunk ^ l7) << 4);
                ldmx4(ah0, h1h + (0 * 16 + arow) * 128 + sw);
                ldmx4(ah1, h1h + (1 * 16 + arow) * 128 + sw);
                ldmx4(al0, h1l + (0 * 16 + arow) * 128 + sw);
                ldmx4(al1, h1l + (1 * 16 + arow) * 128 + sw);
            }
            // B fragments: 8 n-tiles, hi and lo
            uint32_t bh[8][2], bl[8][2];
#pragma unroll
            for (int ntp = 0; ntp < 4; ntp++) {
                int chunk = kt * 2 + bchk;
                uint32_t addr_off = (uint32_t)(ntp * 16 + brow) * 128 + ((uint32_t)(chunk ^ l7) << 4);
                uint32_t r[4];
                ldmx4(r, w2h + addr_off);
                bh[2 * ntp][0] = r[0]; bh[2 * ntp][1] = r[1];
                bh[2 * ntp + 1][0] = r[2]; bh[2 * ntp + 1][1] = r[3];
                ldmx4(r, w2l + addr_off);
                bl[2 * ntp][0] = r[0]; bl[2 * ntp][1] = r[1];
                bl[2 * ntp + 1][0] = r[2]; bl[2 * ntp + 1][1] = r[3];
            }
#pragma unroll
            for (int nt = 0; nt < 8; nt++) {
                mma16816(c[0][nt], ah0, bh[nt]);
                mma16816(c[1][nt], ah1, bh[nt]);
                mma16816(c[0][nt], ah0, bl[nt]);
                mma16816(c[1][nt], ah1, bl[nt]);
                mma16816(c[0][nt], al0, bh[nt]);
                mma16816(c[1][nt], al1, bh[nt]);
            }
        }

        // ---- masked max over 32 rows ----
        // lane holds rows {gr, gr+8, gr+16, gr+24}, cols {8nt+gc, 8nt+gc+1}
        bool a0 = (gr) < np, a1 = (gr + 8) < np, a2 = (gr + 16) < np, a3 = (gr + 24) < np;
        float ve[8], vo[8];
#pragma unroll
        for (int nt = 0; nt < 8; nt++) {
            float e0 = a0 ? c[0][nt][0] : NEGV;
            float e1 = a1 ? c[0][nt][2] : NEGV;
            float e2 = a2 ? c[1][nt][0] : NEGV;
            float e3 = a3 ? c[1][nt][2] : NEGV;
            ve[nt] = fmaxf(fmaxf(e0, e1), fmaxf(e2, e3));
            float o0 = a0 ? c[0][nt][1] : NEGV;
            float o1 = a1 ? c[0][nt][3] : NEGV;
            float o2 = a2 ? c[1][nt][1] : NEGV;
            float o3 = a3 ? c[1][nt][3] : NEGV;
            vo[nt] = fmaxf(fmaxf(o0, o1), fmaxf(o2, o3));
        }
#pragma unroll
        for (int off = 4; off <= 16; off <<= 1) {
#pragma unroll
            for (int nt = 0; nt < 8; nt++) {
                ve[nt] = fmaxf(ve[nt], __shfl_xor_sync(0xffffffffu, ve[nt], off));
                vo[nt] = fmaxf(vo[nt], __shfl_xor_sync(0xffffffffu, vo[nt], off));
            }
        }

        // lanes 0..3 hold all 64 channels: cols 8nt + 2*lane {+0,+1}
        if (lane < 4) {
            bool has = np > 0;
            float* orow = out + (size_t)p * 64;
#pragma unroll
            for (int nt = 0; nt < 8; nt++) {
                int col = nt * 8 + 2 * lane;
                float b0 = sb2[col], b1 = sb2[col + 1];
                orow[col]     = has ? fmaxf(ve[nt] + b0, 0.0f) : NEGV;
                orow[col + 1] = has ? fmaxf(vo[nt] + b1, 0.0f) : NEGV;
            }
        }
        __syncwarp();   // h1 readers done before next tile's stores
    }
}

// ---------------------------------------------------------------------------
extern "C" void kernel_launch(void* const* d_in, const int* in_sizes, int n_in,
                              void* d_out, int out_size)
{
    const float4* pillars = (const float4*)d_in[0];
    const int*    coords  = (const int*)d_in[1];
    const int*    npts    = (const int*)d_in[2];
    const float*  W1 = (const float*)d_in[3];
    const float*  b1 = (const float*)d_in[4];
    const float*  g1 = (const float*)d_in[5];
    const float*  be1 = (const float*)d_in[6];
    const float*  m1 = (const float*)d_in[7];
    const float*  v1 = (const float*)d_in[8];
    const float*  W2 = (const float*)d_in[9];
    const float*  b2 = (const float*)d_in[10];
    const float*  g2 = (const float*)d_in[11];
    const float*  be2 = (const float*)d_in[12];
    const float*  m2 = (const float*)d_in[13];
    const float*  v2 = (const float*)d_in[14];

    int P = in_sizes[0] / (MPTS * 4);
    int ntiles = (P + 3) / 4;

    cudaFuncSetAttribute(pfn_mma_kernel, cudaFuncAttributeMaxDynamicSharedMemorySize, DYN_SMEM);

    fold_kernel<<<1, 64>>>(W1, b1, g1, be1, m1, v1, W2, b2, g2, be2, m2, v2);

    int grid = ntiles < 444 ? ntiles : 444;
    pfn_mma_kernel<<<grid, 128, DYN_SMEM>>>(pillars, coords, npts, (float*)d_out, P, ntiles);
}

// round 16
// speedup vs baseline: 9.7909x; 2.3702x over previous
#include <cuda_runtime.h>
#include <cuda_fp16.h>
#include <cstdint>

#define MPTS 32
#define NEGV -1000000000.0f
#define EPSV 1e-5f

// ---------------- folded weights (device scratch) ----------------
__device__ float g_b2f[64];
// W1 image: fp16 [k][n], k-major rows of 64. k=0..6 folded features, k=7 = b1, k=8..15 = 0
__device__ __align__(16) unsigned short g_W1h[16 * 64];
// W2 image: fp16 [n][k], 128B rows, 16B-chunk swizzled: chunk' = chunk ^ (n&7)
__device__ __align__(16) unsigned short g_W2h[64 * 64];

// ---------------- helpers ----------------
__device__ __forceinline__ uint32_t smem_u32(const void* p) {
    uint32_t a;
    asm("{ .reg .u64 t; cvta.to.shared.u64 t, %1; cvt.u32.u64 %0, t; }" : "=r"(a) : "l"(p));
    return a;
}
__device__ __forceinline__ void ldmx4(uint32_t* r, uint32_t addr) {
    asm volatile("ldmatrix.sync.aligned.m8n8.x4.shared.b16 {%0,%1,%2,%3}, [%4];"
                 : "=r"(r[0]), "=r"(r[1]), "=r"(r[2]), "=r"(r[3]) : "r"(addr));
}
__device__ __forceinline__ void mma16816h(float* c, const uint32_t* a, const uint32_t* b) {
    asm volatile("mma.sync.aligned.m16n8k16.row.col.f32.f16.f16.f32 "
                 "{%0,%1,%2,%3}, {%4,%5,%6,%7}, {%8,%9}, {%0,%1,%2,%3};"
                 : "+f"(c[0]), "+f"(c[1]), "+f"(c[2]), "+f"(c[3])
                 : "r"(a[0]), "r"(a[1]), "r"(a[2]), "r"(a[3]), "r"(b[0]), "r"(b[1]));
}
__device__ __forceinline__ uint32_t packh2(float lo, float hi) {
    __half2 h = __floats2half2_rn(lo, hi);
    return *reinterpret_cast<uint32_t*>(&h);
}

// ---------------------------------------------------------------------------
// Fold kernel. <<<1, 64>>>
__global__ void fold_kernel(const float* __restrict__ W1, const float* __restrict__ b1,
                            const float* __restrict__ g1, const float* __restrict__ beta1,
                            const float* __restrict__ m1, const float* __restrict__ v1,
                            const float* __restrict__ W2, const float* __restrict__ b2,
                            const float* __restrict__ g2, const float* __restrict__ beta2,
                            const float* __restrict__ m2, const float* __restrict__ v2)
{
    int c = threadIdx.x;  // 0..63
    float s1 = g1[c] * rsqrtf(v1[c] + EPSV);
    float b1f = (b1[c] - m1[c]) * s1 + beta1[c];
#pragma unroll
    for (int k = 0; k < 16; k++) {
        float w = 0.0f;
        if (k < 7) {
            w = W1[k * 64 + c];
            if (k == 4) w += W1[7 * 64 + c];  // xo duplicated at rows 4,7
            if (k == 5) w += W1[8 * 64 + c];  // yo duplicated at rows 5,8
            w *= s1;
        } else if (k == 7) {
            w = b1f;                           // bias as feature k=7 (feat value 1.0)
        }
        __half h = __float2half_rn(w);
        g_W1h[k * 64 + c] = *reinterpret_cast<unsigned short*>(&h);
    }
    float s2 = g2[c] * rsqrtf(v2[c] + EPSV);
    g_b2f[c] = (b2[c] - m2[c]) * s2 + beta2[c];
    for (int k = 0; k < 64; k++) {
        float w = W2[k * 64 + c] * s2;         // W2^T row n=c
        __half h = __float2half_rn(w);
        int chunk = (k >> 3) ^ (c & 7);
        g_W2h[c * 64 + chunk * 8 + (k & 7)] = *reinterpret_cast<unsigned short*>(&h);
    }
}

// ---------------------------------------------------------------------------
// Main kernel: warp = pillar. Both layers on tensor cores; h1 lives only in
// registers (layer-1 C fragment == layer-2 A fragment thread mapping).
extern "C" __global__ void __launch_bounds__(128, 4)
pfn_mma2_kernel(const float4* __restrict__ pillars,
                const int* __restrict__ coords,
                const int* __restrict__ npts_arr,
                float* __restrict__ out,
                int P, int ntiles)
{
    __shared__ __align__(128) unsigned short sW2[64 * 64];
    __shared__ float sb2[64];

    int tid = threadIdx.x, warp = tid >> 5, lane = tid & 31;
    for (int i = tid; i < 512; i += 128)
        ((uint4*)sW2)[i] = ((const uint4*)g_W2h)[i];
    if (tid < 64) sb2[tid] = g_b2f[tid];
    __syncthreads();

    uint32_t w2base = smem_u32(sW2);
    int l7 = lane & 7;
    int c = lane & 3;              // fragment col group
    int gr = lane >> 2;            // fragment row 0..7
    int bsub = lane >> 3;
    int brow = ((bsub >> 1) << 3) + l7;
    int bchk = bsub & 1;
    bool ceven = (c & 1) == 0;

    // ---- hoisted W1 B-fragments: b0 = (W1h[2c][n], W1h[2c+1][n]), n = nt*8+gr.
    // (b1 reg of the k16 B-fragment covers k=2c+8..9 which is all zero.)
    uint32_t w1f[8];
#pragma unroll
    for (int nt = 0; nt < 8; nt++) {
        int n = nt * 8 + gr;
        unsigned short lo = g_W1h[(2 * c) * 64 + n];
        unsigned short hi = g_W1h[(2 * c + 1) * 64 + n];
        w1f[nt] = (uint32_t)lo | ((uint32_t)hi << 16);
    }

    for (int tile = blockIdx.x; tile < ntiles; tile += gridDim.x) {
        int p = tile * 4 + warp;
        if (p >= P) continue;                  // warp-uniform

        float4 pt = pillars[(size_t)p * MPTS + lane];
        int cy = coords[2 * p + 0];
        int cx = coords[2 * p + 1];
        int np = npts_arr[p];
        bool active = lane < np;

        float zs = active ? pt.z : 0.0f;
#pragma unroll
        for (int off = 16; off; off >>= 1) zs += __shfl_xor_sync(0xffffffffu, zs, off);
        float zmean = zs / (float)max(np, 1);
        float xc = ((float)cx + 0.5f) * 0.16f + (-51.2f);
        float yc = ((float)cy + 0.5f) * 0.16f + (-51.2f);

        // ---- A1 fragments: row gr+8j, features k = 2c (lo), 2c+1 (hi).
        // c=0:(x,y) c=1:(z,r) c=2:(x-xc, y-yc) c=3:(z-zmean, 1.0[bias feat])
        uint32_t a1[4];
#pragma unroll
        for (int j = 0; j < 4; j++) {
            int src = gr + 8 * j;
            float sx = __shfl_sync(0xffffffffu, pt.x, src);
            float sy = __shfl_sync(0xffffffffu, pt.y, src);
            float sz = __shfl_sync(0xffffffffu, pt.z, src);
            float sr = __shfl_sync(0xffffffffu, pt.w, src);
            float lo = ceven ? sx : sz;
            float hi = ceven ? sy : sr;
            if (c == 2) { lo -= xc; hi -= yc; }
            if (c == 3) { lo -= zmean; hi = 1.0f; }
            a1[j] = packh2(lo, hi);
        }
        uint32_t af0[4] = { a1[0], a1[1], 0u, 0u };   // rows gr, gr+8   (mt0)
        uint32_t af1[4] = { a1[2], a1[3], 0u, 0u };   // rows gr+16,+24  (mt1)

        // ---- layer 1: 16 mmas, K=16 (features 0..7 + zero pad)
        float c1[2][8][4];
#pragma unroll
        for (int mt = 0; mt < 2; mt++)
#pragma unroll
            for (int nt = 0; nt < 8; nt++)
#pragma unroll
                for (int e = 0; e < 4; e++) c1[mt][nt][e] = 0.0f;
#pragma unroll
        for (int nt = 0; nt < 8; nt++) {
            uint32_t bf[2] = { w1f[nt], 0u };
            mma16816h(c1[0][nt], af0, bf);
            mma16816h(c1[1][nt], af1, bf);
        }

        // ---- relu + convert: C1 fragment IS the layer-2 A fragment layout.
        // A2[mt][kt] = {a0,a1,a2,a3}: a0=(gr, ch 16kt+2c,+1)=c1[mt][2kt][0,1],
        // a1=c1[mt][2kt][2,3], a2=c1[mt][2kt+1][0,1], a3=c1[mt][2kt+1][2,3].
        uint32_t a2[2][4][4];
#pragma unroll
        for (int mt = 0; mt < 2; mt++)
#pragma unroll
            for (int kt = 0; kt < 4; kt++) {
                const float* e0 = c1[mt][2 * kt];
                const float* e1 = c1[mt][2 * kt + 1];
                a2[mt][kt][0] = packh2(fmaxf(e0[0], 0.0f), fmaxf(e0[1], 0.0f));
                a2[mt][kt][1] = packh2(fmaxf(e0[2], 0.0f), fmaxf(e0[3], 0.0f));
                a2[mt][kt][2] = packh2(fmaxf(e1[0], 0.0f), fmaxf(e1[1], 0.0f));
                a2[mt][kt][3] = packh2(fmaxf(e1[2], 0.0f), fmaxf(e1[3], 0.0f));
            }

        // ---- layer 2: fp16 1-pass, 64 mmas; B via validated swizzled ldmatrix
        float c2[2][8][4];
#pragma unroll
        for (int mt = 0; mt < 2; mt++)
#pragma unroll
            for (int nt = 0; nt < 8; nt++)
#pragma unroll
                for (int e = 0; e < 4; e++) c2[mt][nt][e] = 0.0f;
#pragma unroll
        for (int kt = 0; kt < 4; kt++) {
            uint32_t bh[8][2];
            int chunk = kt * 2 + bchk;
#pragma unroll
            for (int ntp = 0; ntp < 4; ntp++) {
                uint32_t addr = w2base + (uint32_t)(ntp * 16 + brow) * 128
                              + ((uint32_t)(chunk ^ l7) << 4);
                uint32_t r[4];
                ldmx4(r, addr);
                bh[2 * ntp][0] = r[0]; bh[2 * ntp][1] = r[1];
                bh[2 * ntp + 1][0] = r[2]; bh[2 * ntp + 1][1] = r[3];
            }
#pragma unroll
            for (int nt = 0; nt < 8; nt++) {
                mma16816h(c2[0][nt], a2[0][kt], bh[nt]);
                mma16816h(c2[1][nt], a2[1][kt], bh[nt]);
            }
        }

        // ---- masked max over 32 rows (validated epilogue) ----
        bool a0 = (gr) < np, a1m = (gr + 8) < np, a2m = (gr + 16) < np, a3m = (gr + 24) < np;
        float ve[8], vo[8];
#pragma unroll
        for (int nt = 0; nt < 8; nt++) {
            float e0 = a0 ? c2[0][nt][0] : NEGV;
            float e1 = a1m ? c2[0][nt][2] : NEGV;
            float e2 = a2m ? c2[1][nt][0] : NEGV;
            float e3 = a3m ? c2[1][nt][2] : NEGV;
            ve[nt] = fmaxf(fmaxf(e0, e1), fmaxf(e2, e3));
            float o0 = a0 ? c2[0][nt][1] : NEGV;
            float o1 = a1m ? c2[0][nt][3] : NEGV;
            float o2 = a2m ? c2[1][nt][1] : NEGV;
            float o3 = a3m ? c2[1][nt][3] : NEGV;
            vo[nt] = fmaxf(fmaxf(o0, o1), fmaxf(o2, o3));
        }
#pragma unroll
        for (int off = 4; off <= 16; off <<= 1) {
#pragma unroll
            for (int nt = 0; nt < 8; nt++) {
                ve[nt] = fmaxf(ve[nt], __shfl_xor_sync(0xffffffffu, ve[nt], off));
                vo[nt] = fmaxf(vo[nt], __shfl_xor_sync(0xffffffffu, vo[nt], off));
            }
        }
        if (lane < 4) {
            bool has = np > 0;
            float* orow = out + (size_t)p * 64;
#pragma unroll
            for (int nt = 0; nt < 8; nt++) {
                int col = nt * 8 + 2 * lane;
                float b0 = sb2[col], b1 = sb2[col + 1];
                orow[col]     = has ? fmaxf(ve[nt] + b0, 0.0f) : NEGV;
                orow[col + 1] = has ? fmaxf(vo[nt] + b1, 0.0f) : NEGV;
            }
        }
    }
}

// ---------------------------------------------------------------------------
extern "C" void kernel_launch(void* const* d_in, const int* in_sizes, int n_in,
                              void* d_out, int out_size)
{
    const float4* pillars = (const float4*)d_in[0];
    const int*    coords  = (const int*)d_in[1];
    const int*    npts    = (const int*)d_in[2];
    const float*  W1 = (const float*)d_in[3];
    const float*  b1 = (const float*)d_in[4];
    const float*  g1 = (const float*)d_in[5];
    const float*  be1 = (const float*)d_in[6];
    const float*  m1 = (const float*)d_in[7];
    const float*  v1 = (const float*)d_in[8];
    const float*  W2 = (const float*)d_in[9];
    const float*  b2 = (const float*)d_in[10];
    const float*  g2 = (const float*)d_in[11];
    const float*  be2 = (const float*)d_in[12];
    const float*  m2 = (const float*)d_in[13];
    const float*  v2 = (const float*)d_in[14];

    int P = in_sizes[0] / (MPTS * 4);
    int ntiles = (P + 3) / 4;

    fold_kernel<<<1, 64>>>(W1, b1, g1, be1, m1, v1, W2, b2, g2, be2, m2, v2);

    int grid = ntiles < 592 ? ntiles : 592;
    pfn_mma2_kernel<<<grid, 128>>>(pillars, coords, npts, (float*)d_out, P, ntiles);
}